// round 10
// baseline (speedup 1.0000x reference)
#include <cuda_runtime.h>
#include <cstdint>

#define BB 16
#define VV 8
#define SS 256
#define KK 66
#define NSEQ 128                 // B*V
#define CRF_BLOCKS 128
#define AM_BLOCKS 600
#define THREADS 128
#define ROWS (BB*SS*SS)          // 1,048,576 argmax rows
#define RPI 16                   // rows per warp-iteration (argmax)

__device__ float g_part[NSEQ];
__device__ unsigned int g_cnt;   // zero-init; last CRF block resets after use

__device__ __forceinline__ void ffma2(unsigned long long& d,
                                      unsigned long long a,
                                      unsigned long long b)
{
    asm("fma.rn.f32x2 %0, %1, %2, %0;" : "+l"(d) : "l"(a), "l"(b));
}

__global__ void __launch_bounds__(THREADS, 2) fused_kernel(
    const float* __restrict__ lp,          // log_pa (B,S,S,K)
    const float* __restrict__ score,       // (B,S,S,K)
    const int*   __restrict__ v_label,     // (B,V)
    const int*   __restrict__ orig_l,      // (B,)
    const int*   __restrict__ role_label,  // (B,V,S)
    const float* __restrict__ start_t,     // (K,)
    const float* __restrict__ trans,       // (K,K)
    const float* __restrict__ end_t,       // (K,)
    float* __restrict__ out)               // [0]=loss, [1..]=pred_idx
{
    extern __shared__ float sE[];          // SS*KK floats = exp(a_score)
    __shared__ __align__(16) float sA[2][72];
    __shared__ int   sTag[SS];
    __shared__ float sRed[THREADS];
    __shared__ float sScale[2];            // [0]=1/m, [1]=log(m)
    __shared__ int   sLast;

    const int tid  = threadIdx.x;
    const int lane = tid & 31;

    if (blockIdx.x >= CRF_BLOCKS) {
        // ============================ argmax path ============================
        const int gw = (int)(blockIdx.x - CRF_BLOCKS) * (THREADS / 32) + (tid >> 5);
        const int nw = AM_BLOCKS * (THREADS / 32);

        for (int base = gw * RPI; base < ROWS; base += nw * RPI) {
            float best[RPI]; int bi[RPI];
#pragma unroll
            for (int r = 0; r < RPI; ++r) {
                const float* p = lp + (size_t)(base + r) * KK + lane;
                float v0 = __ldg(p);
                float v1 = __ldg(p + 32);
                best[r] = v0; bi[r] = lane;
                if (v1 > best[r]) { best[r] = v1; bi[r] = lane + 32; }
                if (lane < 2) {
                    float v2 = __ldg(p + 64);
                    if (v2 > best[r]) { best[r] = v2; bi[r] = lane + 64; }
                }
            }
#pragma unroll
            for (int r = 0; r < RPI; ++r) {
                unsigned kb = __float_as_uint(best[r]);
                kb = (kb & 0x80000000u) ? ~kb : (kb | 0x80000000u);
                unsigned kmax = __reduce_max_sync(0xffffffffu, kb);
                unsigned cand = (kb == kmax) ? (unsigned)bi[r] : 0xffffffffu;
                unsigned imin = __reduce_min_sync(0xffffffffu, cand);
                if (lane == 0) out[1 + base + r] = (float)imin;
            }
        }
        return;
    }

    // =============================== CRF path ===============================
    const int n = blockIdx.x;
    const int b = n >> 3;                   // / VV
    const int qrow = v_label[n];
    const int L = orig_l[b];                // >= S/2 >= 2
    const float* asc = score + ((size_t)b * SS + qrow) * SS * KK;

    // tags + pad init
    for (int t = tid; t < L; t += THREADS) sTag[t] = role_label[(size_t)n * SS + t];
    if (tid < 6) { sA[0][66 + tid] = 0.f; sA[1][66 + tid] = 0.f; }
    __syncthreads();

    // stage E = exp(a_score): flat float4 copy (full tile; t>=L harmless)
    {
        const float4* s4 = (const float4*)asc;
        float4* d4 = (float4*)sE;
        for (int i4 = tid; i4 < (SS * KK) / 4; i4 += THREADS) {
            float4 v = __ldg(s4 + i4);
            v.x = __expf(v.x); v.y = __expf(v.y);
            v.z = __expf(v.z); v.w = __expf(v.w);
            d4[i4] = v;
        }
    }

    // numerator: emission + transition gold path
    float acc = 0.f;
    for (int t = tid; t < L; t += THREADS)
        acc += __ldg(asc + t * KK + sTag[t]);
    for (int t = tid + 1; t < L; t += THREADS)
        acc += __ldg(trans + sTag[t - 1] * KK + sTag[t]);
    sRed[tid] = acc;

    // packed exp(trans) column: T2[p] = (exp(T[2p][j]), exp(T[2p+1][j]))
    unsigned long long T2[34];
    if (tid < 66) {
#pragma unroll
        for (int p = 0; p < 34; ++p) {
            int i0 = 2 * p, i1 = 2 * p + 1;
            float lo = (i0 < 66) ? __expf(__ldg(trans + i0 * KK + tid)) : 0.f;
            float hi = (i1 < 66) ? __expf(__ldg(trans + i1 * KK + tid)) : 0.f;
            asm("mov.b64 %0, {%1, %2};" : "=l"(T2[p]) : "f"(lo), "f"(hi));
        }
    } else {
#pragma unroll
        for (int p = 0; p < 34; ++p) T2[p] = 0ull;
    }

    __syncthreads();
    for (int s = 64; s > 0; s >>= 1) {      // deterministic tree reduce
        if (tid < s) sRed[tid] += sRed[tid + s];
        __syncthreads();
    }
    float numer = 0.f;
    if (tid == 0)
        numer = sRed[0] + __ldg(start_t + sTag[0]) + __ldg(end_t + sTag[L - 1]);

    // alpha0 (exp domain)
    if (tid < 66) sA[0][tid] = __expf(start_t[tid]) * sE[tid];
    __syncthreads();

    float* Ac = sA[0];
    float* An = sA[1];
    float Cl = 0.f;
    for (int t = 1; t < L; ++t) {
        float inv = 1.f;
        if ((t & 3) == 0) {                 // renormalize every 4 steps
            if (tid < 32) {
                float m = fmaxf(Ac[tid], Ac[tid + 32]);
                if (tid < 2) m = fmaxf(m, Ac[tid + 64]);
#pragma unroll
                for (int off = 16; off > 0; off >>= 1)
                    m = fmaxf(m, __shfl_down_sync(0xffffffffu, m, off));
                if (tid == 0) { sScale[0] = 1.f / m; sScale[1] = __logf(m); }
            }
            __syncthreads();
            inv = sScale[0];
            Cl += sScale[1];
        }
        if (tid < 66) {
            // batch ALL alpha loads into registers first (breaks load-use serialization)
            const ulonglong2* A2 = (const ulonglong2*)Ac;
            unsigned long long q0[17], q1[17];
#pragma unroll
            for (int ii = 0; ii < 17; ++ii) { ulonglong2 v = A2[ii]; q0[ii] = v.x; q1[ii] = v.y; }
            unsigned long long acc0 = 0ull, acc1 = 0ull;  // packed (0.f, 0.f)
#pragma unroll
            for (int ii = 0; ii < 17; ++ii) {
                ffma2(acc0, q0[ii], T2[2 * ii]);
                ffma2(acc1, q1[ii], T2[2 * ii + 1]);
            }
            float f0, f1, f2, f3;
            asm("mov.b64 {%0, %1}, %2;" : "=f"(f0), "=f"(f1) : "l"(acc0));
            asm("mov.b64 {%0, %1}, %2;" : "=f"(f2), "=f"(f3) : "l"(acc1));
            float s = (f0 + f2) + (f1 + f3);
            An[tid] = s * inv * sE[t * KK + tid];
        }
        __syncthreads();
        float* tmp = Ac; Ac = An; An = tmp;
    }

    // log_z = Cl + log( sum_j A[j] * exp(end_t[j]) )
    float val = 0.f;
    if (tid < 66) val = Ac[tid] * __expf(end_t[tid]);
    sRed[tid] = val;
    __syncthreads();
    for (int s = 64; s > 0; s >>= 1) {
        if (tid < s) sRed[tid] += sRed[tid + s];
        __syncthreads();
    }
    if (tid == 0) {
        float logz = Cl + __logf(sRed[0]);
        g_part[n] = numer - logz;
    }

    // last CRF block finalizes the loss
    __threadfence();
    if (tid == 0) {
        unsigned done = atomicAdd(&g_cnt, 1u);
        sLast = (done == NSEQ - 1);
    }
    __syncthreads();
    if (sLast) {
        __threadfence();
        sRed[tid] = g_part[tid];
        __syncthreads();
        for (int s = 64; s > 0; s >>= 1) {
            if (tid < s) sRed[tid] += sRed[tid + s];
            __syncthreads();
        }
        if (tid == 0) {
            out[0] = sRed[0] / (float)NSEQ;
            atomicExch(&g_cnt, 0u);         // reset for next graph replay
        }
    }
}

extern "C" void kernel_launch(void* const* d_in, const int* in_sizes, int n_in,
                              void* d_out, int out_size)
{
    (void)in_sizes; (void)n_in; (void)out_size;
    const float* log_pa     = (const float*)d_in[0];
    const float* score      = (const float*)d_in[1];
    const int*   v_label    = (const int*)d_in[2];
    // d_in[3] = v_l (unused by reference)
    const int*   orig_l     = (const int*)d_in[4];
    const int*   role_label = (const int*)d_in[5];
    const float* start_t    = (const float*)d_in[6];
    const float* trans      = (const float*)d_in[7];
    const float* end_t      = (const float*)d_in[8];
    float* out = (float*)d_out;

    const int smem = SS * KK * (int)sizeof(float);  // 67584 B
    cudaFuncSetAttribute((const void*)fused_kernel,
                         cudaFuncAttributeMaxDynamicSharedMemorySize, smem);

    fused_kernel<<<CRF_BLOCKS + AM_BLOCKS, THREADS, smem>>>(
        log_pa, score, v_label, orig_l, role_label, start_t, trans, end_t, out);
}